// round 1
// baseline (speedup 1.0000x reference)
#include <cuda_runtime.h>

// Problem shape (fixed by the dataset)
#define BB 4
#define SS 256
#define EE 256
#define MM (BB * SS)        // 1024 "rows" of x

// Scratch: pi[m,f] and (pj[m,f] + b[f]) — 1 MB each
__device__ float g_pi [MM * EE];
__device__ float g_pjb[MM * EE];

// ---------------------------------------------------------------------------
// Kernel 1: dual GEMM
//   pi[m,f]  = sum_e x[m,e] * W[f, e]        (W row-major, stride 2*EE)
//   pjb[m,f] = sum_e x[m,e] * W[f, EE+e] + b[f]
// Tiling: BM=32 (m), BN=64 (f), BK=16. 256 threads, thread tile 2x4 (x2 outs).
// Grid: (1024/32) x (256/64) = 32 x 4 = 128 blocks.
// ---------------------------------------------------------------------------
#define BM 32
#define BN 64
#define BK 16

__global__ __launch_bounds__(256)
void gemm_kernel(const float* __restrict__ x,
                 const float* __restrict__ W,
                 const float* __restrict__ bias)
{
    __shared__ float s_x [BK][BM + 4];   // [k][m], padded (row stride 36 floats)
    __shared__ float s_w1[BK][BN + 4];   // [k][f], padded (row stride 68 floats, 16B-aligned rows)
    __shared__ float s_w2[BK][BN + 4];

    const int m0  = blockIdx.x * BM;
    const int f0  = blockIdx.y * BN;
    const int tid = threadIdx.x;
    const int ty  = tid >> 4;    // 0..15 -> m dimension (2 rows each)
    const int tx  = tid & 15;    // 0..15 -> f dimension (4 cols each)

    float acc1[2][4] = {};
    float acc2[2][4] = {};

    for (int k0 = 0; k0 < EE; k0 += BK) {
        // Load x tile: BM*BK = 512 floats, 2 per thread
        #pragma unroll
        for (int r = 0; r < 2; ++r) {
            int idx = tid + r * 256;
            int m = idx >> 4, k = idx & 15;
            s_x[k][m] = x[(size_t)(m0 + m) * EE + k0 + k];
        }
        // Load W tiles: BN*BK = 1024 floats each, 4 per thread
        #pragma unroll
        for (int r = 0; r < 4; ++r) {
            int idx = tid + r * 256;
            int f = idx >> 4, k = idx & 15;
            const float* wrow = W + (size_t)(f0 + f) * (2 * EE) + (k0 + k);
            s_w1[k][f] = wrow[0];
            s_w2[k][f] = wrow[EE];
        }
        __syncthreads();

        #pragma unroll
        for (int k = 0; k < BK; ++k) {
            float a0 = s_x[k][ty * 2 + 0];
            float a1 = s_x[k][ty * 2 + 1];
            float4 b1 = *(const float4*)&s_w1[k][tx * 4];
            float4 b2 = *(const float4*)&s_w2[k][tx * 4];

            acc1[0][0] += a0 * b1.x; acc1[0][1] += a0 * b1.y;
            acc1[0][2] += a0 * b1.z; acc1[0][3] += a0 * b1.w;
            acc1[1][0] += a1 * b1.x; acc1[1][1] += a1 * b1.y;
            acc1[1][2] += a1 * b1.z; acc1[1][3] += a1 * b1.w;

            acc2[0][0] += a0 * b2.x; acc2[0][1] += a0 * b2.y;
            acc2[0][2] += a0 * b2.z; acc2[0][3] += a0 * b2.w;
            acc2[1][0] += a1 * b2.x; acc2[1][1] += a1 * b2.y;
            acc2[1][2] += a1 * b2.z; acc2[1][3] += a1 * b2.w;
        }
        __syncthreads();
    }

    float4 bi = *(const float4*)&bias[f0 + tx * 4];

    #pragma unroll
    for (int i = 0; i < 2; ++i) {
        int m = m0 + ty * 2 + i;
        float4 v1 = make_float4(acc1[i][0], acc1[i][1], acc1[i][2], acc1[i][3]);
        float4 v2 = make_float4(acc2[i][0] + bi.x, acc2[i][1] + bi.y,
                                acc2[i][2] + bi.z, acc2[i][3] + bi.w);
        *(float4*)&g_pi [(size_t)m * EE + f0 + tx * 4] = v1;
        *(float4*)&g_pjb[(size_t)m * EE + f0 + tx * 4] = v2;
    }
}

// ---------------------------------------------------------------------------
// Kernel 2: broadcast add, out[b,i,j,e] = pi[b,i,e] + pjb[b,j,e]
// Block handles (b, 8 i-rows, 32 j-rows); stages both tiles in SMEM so global
// reads are ~40KB/block while writing 256KB/block. Pure HBM-write-bound.
// Grid: (256/32, 256/8, 4) = (8, 32, 4) = 1024 blocks, 256 threads.
// ---------------------------------------------------------------------------
#define TI 8
#define TJ 32
#define E4 (EE / 4)   // 64 float4 per row

__global__ __launch_bounds__(256)
void add_kernel(float* __restrict__ out)
{
    __shared__ float4 s_pi[TI * E4];   // 8 KB
    __shared__ float4 s_pj[TJ * E4];   // 32 KB

    const int b  = blockIdx.z;
    const int i0 = blockIdx.y * TI;
    const int j0 = blockIdx.x * TJ;
    const int tid = threadIdx.x;

    const float4* pi4 = (const float4*)g_pi  + (size_t)(b * SS + i0) * E4;
    const float4* pj4 = (const float4*)g_pjb + (size_t)(b * SS + j0) * E4;

    // Stage tiles: 512 + 2048 float4, 256 threads
    s_pi[tid]       = pi4[tid];
    s_pi[tid + 256] = pi4[tid + 256];
    #pragma unroll
    for (int r = 0; r < 8; ++r)
        s_pj[tid + r * 256] = pj4[tid + r * 256];
    __syncthreads();

    const int e4  = tid & 63;   // float4 column within row
    const int sub = tid >> 6;   // 0..3: which (i,j) pair in each group of 4

    float4* out4 = (float4*)out + ((size_t)(b * SS + i0) * SS + j0) * E4;

    #pragma unroll 8
    for (int p = sub; p < TI * TJ; p += 4) {
        int i = p >> 5;          // p / TJ
        int j = p & 31;          // p % TJ
        float4 a = s_pi[i * E4 + e4];
        float4 c = s_pj[j * E4 + e4];
        float4 v = make_float4(a.x + c.x, a.y + c.y, a.z + c.z, a.w + c.w);
        out4[((size_t)i * SS + j) * E4 + e4] = v;
    }
}

// ---------------------------------------------------------------------------
extern "C" void kernel_launch(void* const* d_in, const int* in_sizes, int n_in,
                              void* d_out, int out_size)
{
    const float* x    = (const float*)d_in[0];   // component_repr [4,256,256]
    const float* W    = (const float*)d_in[1];   // W [256,512]
    const float* bias = (const float*)d_in[2];   // b [256]
    float* out = (float*)d_out;                  // [4,256,256,256]

    dim3 gGemm(MM / BM, EE / BN);                // 32 x 4
    gemm_kernel<<<gGemm, 256>>>(x, W, bias);

    dim3 gAdd(SS / TJ, SS / TI, BB);             // 8 x 32 x 4
    add_kernel<<<gAdd, 256>>>(out);
}

// round 2
// speedup vs baseline: 1.1339x; 1.1339x over previous
#include <cuda_runtime.h>

// Problem shape (fixed by the dataset)
#define BB 4
#define SS 256
#define EE 256
#define MM (BB * SS)        // 1024 "rows" of x

// Scratch: pi[m,f] and (pj[m,f] + b[f]) — 1 MB each
__device__ float g_pi [MM * EE];
__device__ float g_pjb[MM * EE];

// ---------------------------------------------------------------------------
// Kernel 1: dual GEMM, double-buffered smem + register prefetch.
//   pi[m,f]  = sum_e x[m,e] * W[f, e]
//   pjb[m,f] = sum_e x[m,e] * W[f, EE+e] + b[f]
// BM=32, BN=64, BK=32, 256 threads, thread tile 2(m) x 4(f) x 2 outputs.
// Grid: (1024/32) x (256/64) = 128 blocks (one wave).
// ---------------------------------------------------------------------------
#define BM 32
#define BN 64
#define BK 32
#define NT (EE / BK)       // 8 K-chunks

#define XS 40              // s_x row stride (floats): 160B, 16B-aligned
#define WS 68              // s_w row stride (floats): 272B, 16B-aligned

__global__ __launch_bounds__(256)
void gemm_kernel(const float* __restrict__ x,
                 const float* __restrict__ W,
                 const float* __restrict__ bias)
{
    __shared__ float s_x [2][BM][XS];
    __shared__ float s_w1[2][BK][WS];
    __shared__ float s_w2[2][BK][WS];

    const int m0  = blockIdx.x * BM;
    const int f0  = blockIdx.y * BN;
    const int tid = threadIdx.x;
    const int ty  = tid >> 4;    // 0..15 -> m (2 rows each)
    const int tx  = tid & 15;    // 0..15 -> f (4 cols each)

    // load indices
    const int lm  = tid >> 3;    // 0..31  (x tile row)
    const int lkv = tid & 7;     // 0..7   (k float4 within row)
    const int lf  = tid >> 3;    // 0..31  (w tile row base; +32 with r=1)

    float4 rx, rw1[2], rw2[2];

    // ---- prologue: load chunk 0 into registers ----
    {
        const int k0 = 0;
        rx = *(const float4*)&x[(size_t)(m0 + lm) * EE + k0 + lkv * 4];
        #pragma unroll
        for (int r = 0; r < 2; ++r) {
            int f = lf + r * 32;
            const float* wrow = W + (size_t)(f0 + f) * (2 * EE) + k0 + lkv * 4;
            rw1[r] = *(const float4*)(wrow);
            rw2[r] = *(const float4*)(wrow + EE);
        }
    }
    // store chunk 0 to buffer 0
    {
        *(float4*)&s_x[0][lm][lkv * 4] = rx;
        #pragma unroll
        for (int r = 0; r < 2; ++r) {
            int f = lf + r * 32;
            s_w1[0][lkv * 4 + 0][f] = rw1[r].x;
            s_w1[0][lkv * 4 + 1][f] = rw1[r].y;
            s_w1[0][lkv * 4 + 2][f] = rw1[r].z;
            s_w1[0][lkv * 4 + 3][f] = rw1[r].w;
            s_w2[0][lkv * 4 + 0][f] = rw2[r].x;
            s_w2[0][lkv * 4 + 1][f] = rw2[r].y;
            s_w2[0][lkv * 4 + 2][f] = rw2[r].z;
            s_w2[0][lkv * 4 + 3][f] = rw2[r].w;
        }
    }
    __syncthreads();

    float acc1[2][4] = {};
    float acc2[2][4] = {};

    for (int t = 0; t < NT; ++t) {
        const int buf = t & 1;

        // prefetch next chunk into registers (LDGs issued before compute)
        if (t + 1 < NT) {
            const int k0 = (t + 1) * BK;
            rx = *(const float4*)&x[(size_t)(m0 + lm) * EE + k0 + lkv * 4];
            #pragma unroll
            for (int r = 0; r < 2; ++r) {
                int f = lf + r * 32;
                const float* wrow = W + (size_t)(f0 + f) * (2 * EE) + k0 + lkv * 4;
                rw1[r] = *(const float4*)(wrow);
                rw2[r] = *(const float4*)(wrow + EE);
            }
        }

        // compute on current buffer
        #pragma unroll
        for (int k = 0; k < BK; ++k) {
            float a0 = s_x[buf][ty * 2 + 0][k];
            float a1 = s_x[buf][ty * 2 + 1][k];
            float4 b1 = *(const float4*)&s_w1[buf][k][tx * 4];
            float4 b2 = *(const float4*)&s_w2[buf][k][tx * 4];

            acc1[0][0] += a0 * b1.x; acc1[0][1] += a0 * b1.y;
            acc1[0][2] += a0 * b1.z; acc1[0][3] += a0 * b1.w;
            acc1[1][0] += a1 * b1.x; acc1[1][1] += a1 * b1.y;
            acc1[1][2] += a1 * b1.z; acc1[1][3] += a1 * b1.w;

            acc2[0][0] += a0 * b2.x; acc2[0][1] += a0 * b2.y;
            acc2[0][2] += a0 * b2.z; acc2[0][3] += a0 * b2.w;
            acc2[1][0] += a1 * b2.x; acc2[1][1] += a1 * b2.y;
            acc2[1][2] += a1 * b2.z; acc2[1][3] += a1 * b2.w;
        }

        // drain prefetch regs into the other buffer
        if (t + 1 < NT) {
            const int nbuf = (t + 1) & 1;
            *(float4*)&s_x[nbuf][lm][lkv * 4] = rx;
            #pragma unroll
            for (int r = 0; r < 2; ++r) {
                int f = lf + r * 32;
                s_w1[nbuf][lkv * 4 + 0][f] = rw1[r].x;
                s_w1[nbuf][lkv * 4 + 1][f] = rw1[r].y;
                s_w1[nbuf][lkv * 4 + 2][f] = rw1[r].z;
                s_w1[nbuf][lkv * 4 + 3][f] = rw1[r].w;
                s_w2[nbuf][lkv * 4 + 0][f] = rw2[r].x;
                s_w2[nbuf][lkv * 4 + 1][f] = rw2[r].y;
                s_w2[nbuf][lkv * 4 + 2][f] = rw2[r].z;
                s_w2[nbuf][lkv * 4 + 3][f] = rw2[r].w;
            }
            __syncthreads();
        }
    }

    float4 bi = *(const float4*)&bias[f0 + tx * 4];

    #pragma unroll
    for (int i = 0; i < 2; ++i) {
        int m = m0 + ty * 2 + i;
        float4 v1 = make_float4(acc1[i][0], acc1[i][1], acc1[i][2], acc1[i][3]);
        float4 v2 = make_float4(acc2[i][0] + bi.x, acc2[i][1] + bi.y,
                                acc2[i][2] + bi.z, acc2[i][3] + bi.w);
        *(float4*)&g_pi [(size_t)m * EE + f0 + tx * 4] = v1;
        *(float4*)&g_pjb[(size_t)m * EE + f0 + tx * 4] = v2;
    }
}

// ---------------------------------------------------------------------------
// Kernel 2: broadcast add, out[b,i,j,e] = pi[b,i,e] + pjb[b,j,e]
// Block = (b, 8 i-rows, 32 j-rows). pi tile lives in REGISTERS (8 float4 per
// thread), pjb tile in SMEM. Each 16B store now costs 1/8 LDS instead of 2
// => l1tex wavefronts/store drop from ~12 to ~4.5; DRAM becomes sole bound.
// __stcs keeps the 268MB output stream from thrashing L2.
// Grid: (8, 32, 4) = 1024 blocks, 256 threads.
// ---------------------------------------------------------------------------
#define TI 8
#define TJ 32
#define E4 (EE / 4)   // 64 float4 per row

__global__ __launch_bounds__(256)
void add_kernel(float* __restrict__ out)
{
    __shared__ float4 s_pj[TJ * E4];   // 32 KB

    const int b   = blockIdx.z;
    const int i0  = blockIdx.y * TI;
    const int j0  = blockIdx.x * TJ;
    const int tid = threadIdx.x;
    const int e4  = tid & 63;   // float4 column within a row
    const int jq  = tid >> 6;   // 0..3

    const float4* pi4 = (const float4*)g_pi  + (size_t)(b * SS + i0) * E4;
    const float4* pj4 = (const float4*)g_pjb + (size_t)(b * SS + j0) * E4;

    // stage pjb tile in smem (2048 float4, 8 per thread)
    #pragma unroll
    for (int r = 0; r < 8; ++r)
        s_pj[tid + r * 256] = pj4[tid + r * 256];

    // pi tile -> registers (each thread holds its e4-column for all 8 i-rows)
    float4 pi_r[TI];
    #pragma unroll
    for (int i = 0; i < TI; ++i)
        pi_r[i] = pi4[i * E4 + e4];

    __syncthreads();

    float4* out4 = (float4*)out + ((size_t)(b * SS + i0) * SS + j0) * E4;

    #pragma unroll
    for (int jj = 0; jj < TJ / 4; ++jj) {
        int j = jq + jj * 4;
        float4 c = s_pj[j * E4 + e4];
        #pragma unroll
        for (int i = 0; i < TI; ++i) {
            float4 v = make_float4(pi_r[i].x + c.x, pi_r[i].y + c.y,
                                   pi_r[i].z + c.z, pi_r[i].w + c.w);
            __stcs(&out4[((size_t)i * SS + j) * E4 + e4], v);
        }
    }
}

// ---------------------------------------------------------------------------
extern "C" void kernel_launch(void* const* d_in, const int* in_sizes, int n_in,
                              void* d_out, int out_size)
{
    const float* x    = (const float*)d_in[0];   // component_repr [4,256,256]
    const float* W    = (const float*)d_in[1];   // W [256,512]
    const float* bias = (const float*)d_in[2];   // b [256]
    float* out = (float*)d_out;                  // [4,256,256,256]

    dim3 gGemm(MM / BM, EE / BN);                // 32 x 4
    gemm_kernel<<<gGemm, 256>>>(x, W, bias);

    dim3 gAdd(SS / TJ, SS / TI, BB);             // 8 x 32 x 4
    add_kernel<<<gAdd, 256>>>(out);
}